// round 13
// baseline (speedup 1.0000x reference)
#include <cuda_runtime.h>
#include <cuda_fp16.h>
#include <math.h>

#define NN 100000
#define EE 1600000
#define HC 128
#define F2 64
#define NEG_SLOPE 0.2f
#define NB2 ((NN + 511) / 512)   // 196 scan blocks (512 thr)
#define NH 50048                 // gather1/gemm2 pipeline split (64-aligned)

// ---------------- scratch (device globals; no allocation allowed) ----------
__device__ __half g_h1[NN * HC];
__device__ __half g_o1[NN * HC];
__device__ __half g_h2[NN * F2];
__device__ float  g_as1[NN * 4], g_ad1[NN * 4];
__device__ float  g_as2[NN], g_ad2[NN];
__device__ int    g_esrc[EE];
__device__ unsigned g_drk[EE];         // dst | (rank << 17)
__device__ int    g_deg[NN];           // zero at entry (BSS / gather2 tail)
__device__ int    g_roff[NN + 1];
__device__ int    g_bsum[NB2];
__device__ int    g_boff[NB2];
__device__ int    g_tick;
__device__ int    g_csrc[EE];

// ---------------- helpers ---------------------------------------------------
__device__ __forceinline__ float lrelu(float x) {
    return x > 0.f ? x : NEG_SLOPE * x;
}
__device__ __forceinline__ int clampN(int v) {
    return v < 0 ? 0 : (v >= NN ? NN - 1 : v);
}
__device__ __forceinline__ float to_tf32(float x) {
    float r; asm("cvt.rna.tf32.f32 %0, %1;" : "=f"(r) : "f"(x)); return r;
}
__device__ __forceinline__ void mma_tf32(float* c, unsigned a0, unsigned a1,
                                         unsigned a2, unsigned a3,
                                         unsigned b0, unsigned b1) {
    asm volatile(
        "mma.sync.aligned.m16n8k8.row.col.f32.tf32.tf32.f32 "
        "{%0,%1,%2,%3}, {%4,%5,%6,%7}, {%8,%9}, {%0,%1,%2,%3};"
        : "+f"(c[0]), "+f"(c[1]), "+f"(c[2]), "+f"(c[3])
        : "r"(a0), "r"(a1), "r"(a2), "r"(a3), "r"(b0), "r"(b1));
}
__device__ __forceinline__ float4 ldh4(const __half* p) {
    uint2 u = *(const uint2*)p;
    float2 a = __half22float2(*(__half2*)&u.x);
    float2 b = __half22float2(*(__half2*)&u.y);
    return make_float4(a.x, a.y, b.x, b.y);
}
// nc load of 8 consecutive halfs (16B aligned) -> 8 floats
__device__ __forceinline__ void ldh8nc(const __half* p, float* f) {
    uint4 u = __ldg((const uint4*)p);
    float2 a = __half22float2(*(__half2*)&u.x);
    float2 b = __half22float2(*(__half2*)&u.y);
    float2 c = __half22float2(*(__half2*)&u.z);
    float2 d = __half22float2(*(__half2*)&u.w);
    f[0] = a.x; f[1] = a.y; f[2] = b.x; f[3] = b.y;
    f[4] = c.x; f[5] = c.y; f[6] = d.x; f[7] = d.y;
}
// nc load of 16 consecutive halfs (two 16B loads) -> 16 floats
__device__ __forceinline__ void ldh16nc(const __half* p, float* f) {
    ldh8nc(p, f);
    ldh8nc(p + 8, f + 8);
}
__device__ __forceinline__ void sth8(__half* p, const float* f) {
    uint4 u;
    *(__half2*)&u.x = __floats2half2_rn(f[0], f[1]);
    *(__half2*)&u.y = __floats2half2_rn(f[2], f[3]);
    *(__half2*)&u.z = __floats2half2_rn(f[4], f[5]);
    *(__half2*)&u.w = __floats2half2_rn(f[6], f[7]);
    *(uint4*)p = u;
}

// ---------------- edge convert + histogram + rank capture (packed) -----------
__global__ void k_prep(const void* __restrict__ ei) {
    int i = blockIdx.x * blockDim.x + threadIdx.x;
    if (i >= EE) return;
    const int* e32 = (const int*)ei;
    int is64 = 1;
#pragma unroll
    for (int k = 0; k < 8; k++)
        if (e32[2 * k + 1] != 0) is64 = 0;
    int s, d;
    if (is64) {
        const long long* p = (const long long*)ei;
        s = (int)p[i]; d = (int)p[EE + i];
    } else {
        s = e32[i]; d = e32[EE + i];
    }
    s = clampN(s); d = clampN(d);
    g_esrc[i] = s;
    unsigned r = (unsigned)atomicAdd(&g_deg[d], 1);
    g_drk[i] = (unsigned)d | (r << 17);
}

// ---------------- scanA: per-block reduce + last-block scans block sums ------
__global__ void k_scanA() {
    __shared__ int sh[512];
    __shared__ int last;
    int b = blockIdx.x, t = threadIdx.x;
    int i = b * 512 + t;
    sh[t] = (i < NN) ? g_deg[i] : 0;
    __syncthreads();
#pragma unroll
    for (int off = 256; off; off >>= 1) {
        if (t < off) sh[t] += sh[t + off];
        __syncthreads();
    }
    if (t == 0) {
        g_bsum[b] = sh[0];
        __threadfence();
        last = (atomicAdd(&g_tick, 1) == NB2 - 1);
    }
    __syncthreads();
    if (last) {
        int v = (t < NB2) ? g_bsum[t] : 0;
        sh[t] = v;
        __syncthreads();
#pragma unroll
        for (int off = 1; off < 512; off <<= 1) {
            int x = (t >= off) ? sh[t - off] : 0;
            __syncthreads();
            sh[t] += x;
            __syncthreads();
        }
        if (t < NB2) g_boff[t] = sh[t] - v;   // exclusive
    }
}

// ---------------- scan3: in-block scan + offset -> row offsets ---------------
__global__ void k_scan3() {
    __shared__ int sh[512];
    int b = blockIdx.x, t = threadIdx.x;
    int i = b * 512 + t;
    int v = (i < NN) ? g_deg[i] : 0;
    sh[t] = v;
    __syncthreads();
#pragma unroll
    for (int off = 1; off < 512; off <<= 1) {
        int x = (t >= off) ? sh[t - off] : 0;
        __syncthreads();
        sh[t] += x;
        __syncthreads();
    }
    int excl = g_boff[b] + sh[t] - v;
    if (i < NN) {
        g_roff[i] = excl;
        if (i == NN - 1) g_roff[NN] = excl + v;
    }
}

// ---------------- scatter: atomic-free, packed, 2 edges/thread ---------------
__global__ void k_scatter() {
    int base = (blockIdx.x * blockDim.x + threadIdx.x) * 2;
    if (base >= EE) return;
    unsigned v0 = g_drk[base];
    int s0 = g_esrc[base];
    int p0 = g_roff[v0 & 131071u] + (int)(v0 >> 17);
    if (base + 1 < EE) {
        unsigned v1 = g_drk[base + 1];
        int s1 = g_esrc[base + 1];
        int p1 = g_roff[v1 & 131071u] + (int)(v1 >> 17);
        g_csrc[p0] = s0;
        g_csrc[p1] = s1;
    } else {
        g_csrc[p0] = s0;
    }
}

// ---------------- GEMM1 (tf32 mma) + fused att1 epilogue, fp16 C -------------
__global__ void k_gemm1(const float* __restrict__ A, const float* __restrict__ W,
                        __half* __restrict__ C,
                        const float* __restrict__ att_src, const float* __restrict__ att_dst,
                        int M) {
    __shared__ float As[64][36];
    __shared__ float Bs[32][132];
    int tid = threadIdx.x;
    int wid = tid >> 5, lane = tid & 31;
    int wm = wid >> 1, wn = wid & 1;
    int g = lane >> 2, t = lane & 3;
    int row0 = blockIdx.x * 64;
    float c[8][4];
#pragma unroll
    for (int i = 0; i < 8; i++)
#pragma unroll
        for (int j = 0; j < 4; j++) c[i][j] = 0.f;

    for (int k0 = 0; k0 < 128; k0 += 32) {
#pragma unroll
        for (int s = 0; s < 2; s++) {
            int f = tid + s * 256;
            int r = f >> 3, c4 = (f & 7) * 4;
            float4 v = make_float4(0.f, 0.f, 0.f, 0.f);
            if (row0 + r < M) v = *(const float4*)&A[(size_t)(row0 + r) * 128 + k0 + c4];
            v.x = to_tf32(v.x); v.y = to_tf32(v.y);
            v.z = to_tf32(v.z); v.w = to_tf32(v.w);
            *(float4*)&As[r][c4] = v;
        }
#pragma unroll
        for (int s = 0; s < 4; s++) {
            int f = tid + s * 256;
            int r = f >> 5, c4 = (f & 31) * 4;
            float4 v = *(const float4*)&W[(size_t)(k0 + r) * 128 + c4];
            v.x = to_tf32(v.x); v.y = to_tf32(v.y);
            v.z = to_tf32(v.z); v.w = to_tf32(v.w);
            *(float4*)&Bs[r][c4] = v;
        }
        __syncthreads();
#pragma unroll
        for (int kk = 0; kk < 32; kk += 8) {
            int ar = wm * 16;
            unsigned a0 = __float_as_uint(As[ar + g][kk + t]);
            unsigned a1 = __float_as_uint(As[ar + g + 8][kk + t]);
            unsigned a2 = __float_as_uint(As[ar + g][kk + t + 4]);
            unsigned a3 = __float_as_uint(As[ar + g + 8][kk + t + 4]);
#pragma unroll
            for (int nt = 0; nt < 8; nt++) {
                int n0 = wn * 64 + nt * 8;
                unsigned b0 = __float_as_uint(Bs[kk + t][n0 + g]);
                unsigned b1 = __float_as_uint(Bs[kk + t + 4][n0 + g]);
                mma_tf32(c[nt], a0, a1, a2, a3, b0, b1);
            }
        }
        __syncthreads();
    }
    int r1 = row0 + wm * 16 + g;
    int r2 = r1 + 8;
#pragma unroll
    for (int nt = 0; nt < 8; nt++) {
        int col = wn * 64 + nt * 8 + t * 2;
        if (r1 < M) *(__half2*)&C[(size_t)r1 * 128 + col] = __floats2half2_rn(c[nt][0], c[nt][1]);
        if (r2 < M) *(__half2*)&C[(size_t)r2 * 128 + col] = __floats2half2_rn(c[nt][2], c[nt][3]);
    }
    float s1a = 0.f, s1b = 0.f, d1a = 0.f, d1b = 0.f;
    float s2a = 0.f, s2b = 0.f, d2a = 0.f, d2b = 0.f;
#pragma unroll
    for (int nt = 0; nt < 8; nt++) {
        int col = wn * 64 + nt * 8 + t * 2;
        float av0 = att_src[col], av1 = att_src[col + 1];
        float dv0 = att_dst[col], dv1 = att_dst[col + 1];
        float ps1 = c[nt][0] * av0 + c[nt][1] * av1;
        float pd1 = c[nt][0] * dv0 + c[nt][1] * dv1;
        float ps2 = c[nt][2] * av0 + c[nt][3] * av1;
        float pd2 = c[nt][2] * dv0 + c[nt][3] * dv1;
        if (nt < 4) { s1a += ps1; d1a += pd1; s2a += ps2; d2a += pd2; }
        else        { s1b += ps1; d1b += pd1; s2b += ps2; d2b += pd2; }
    }
#pragma unroll
    for (int off = 1; off < 4; off <<= 1) {
        s1a += __shfl_xor_sync(~0u, s1a, off); s1b += __shfl_xor_sync(~0u, s1b, off);
        d1a += __shfl_xor_sync(~0u, d1a, off); d1b += __shfl_xor_sync(~0u, d1b, off);
        s2a += __shfl_xor_sync(~0u, s2a, off); s2b += __shfl_xor_sync(~0u, s2b, off);
        d2a += __shfl_xor_sync(~0u, d2a, off); d2b += __shfl_xor_sync(~0u, d2b, off);
    }
    if (t == 0) {
        int ha = 2 * wn, hb = 2 * wn + 1;
        if (r1 < M) {
            g_as1[r1 * 4 + ha] = s1a; g_as1[r1 * 4 + hb] = s1b;
            g_ad1[r1 * 4 + ha] = d1a; g_ad1[r1 * 4 + hb] = d1b;
        }
        if (r2 < M) {
            g_as1[r2 * 4 + ha] = s2a; g_as1[r2 * 4 + hb] = s2b;
            g_ad1[r2 * 4 + ha] = d2a; g_ad1[r2 * 4 + hb] = d2b;
        }
    }
}

// ---------------- GEMM2 (tf32 mma, fp16 A/C) + fused att2, row-range ---------
__global__ void k_gemm2(const __half* __restrict__ A, const float* __restrict__ W,
                        __half* __restrict__ C,
                        const float* __restrict__ att_src, const float* __restrict__ att_dst,
                        int base, int M) {
    __shared__ float As[64][36];
    __shared__ float Bs[32][68];
    __shared__ float sp[64][2], dp[64][2];
    int tid = threadIdx.x;
    int wid = tid >> 5, lane = tid & 31;
    int wm = wid >> 1, wn = wid & 1;
    int g = lane >> 2, t = lane & 3;
    int row0 = base + blockIdx.x * 64;
    float c[4][4];
#pragma unroll
    for (int i = 0; i < 4; i++)
#pragma unroll
        for (int j = 0; j < 4; j++) c[i][j] = 0.f;

    for (int k0 = 0; k0 < 128; k0 += 32) {
#pragma unroll
        for (int s = 0; s < 2; s++) {
            int f = tid + s * 256;
            int r = f >> 3, c4 = (f & 7) * 4;
            float4 v = make_float4(0.f, 0.f, 0.f, 0.f);
            if (row0 + r < M) {
                float4 u = ldh4(&A[(size_t)(row0 + r) * 128 + k0 + c4]);
                v.x = u.x > 0.f ? u.x : expm1f(u.x);
                v.y = u.y > 0.f ? u.y : expm1f(u.y);
                v.z = u.z > 0.f ? u.z : expm1f(u.z);
                v.w = u.w > 0.f ? u.w : expm1f(u.w);
            }
            v.x = to_tf32(v.x); v.y = to_tf32(v.y);
            v.z = to_tf32(v.z); v.w = to_tf32(v.w);
            *(float4*)&As[r][c4] = v;
        }
#pragma unroll
        for (int s = 0; s < 2; s++) {
            int f = tid + s * 256;
            int r = f >> 4, c4 = (f & 15) * 4;
            float4 v = *(const float4*)&W[(size_t)(k0 + r) * 64 + c4];
            v.x = to_tf32(v.x); v.y = to_tf32(v.y);
            v.z = to_tf32(v.z); v.w = to_tf32(v.w);
            *(float4*)&Bs[r][c4] = v;
        }
        __syncthreads();
#pragma unroll
        for (int kk = 0; kk < 32; kk += 8) {
            int ar = wm * 16;
            unsigned a0 = __float_as_uint(As[ar + g][kk + t]);
            unsigned a1 = __float_as_uint(As[ar + g + 8][kk + t]);
            unsigned a2 = __float_as_uint(As[ar + g][kk + t + 4]);
            unsigned a3 = __float_as_uint(As[ar + g + 8][kk + t + 4]);
#pragma unroll
            for (int nt = 0; nt < 4; nt++) {
                int n0 = wn * 32 + nt * 8;
                unsigned b0 = __float_as_uint(Bs[kk + t][n0 + g]);
                unsigned b1 = __float_as_uint(Bs[kk + t + 4][n0 + g]);
                mma_tf32(c[nt], a0, a1, a2, a3, b0, b1);
            }
        }
        __syncthreads();
    }
    int r1 = row0 + wm * 16 + g;
    int r2 = r1 + 8;
    float s1 = 0.f, d1 = 0.f, s2 = 0.f, d2 = 0.f;
#pragma unroll
    for (int nt = 0; nt < 4; nt++) {
        int col = wn * 32 + nt * 8 + t * 2;
        if (r1 < M) *(__half2*)&C[(size_t)r1 * 64 + col] = __floats2half2_rn(c[nt][0], c[nt][1]);
        if (r2 < M) *(__half2*)&C[(size_t)r2 * 64 + col] = __floats2half2_rn(c[nt][2], c[nt][3]);
        float av0 = att_src[col], av1 = att_src[col + 1];
        float dv0 = att_dst[col], dv1 = att_dst[col + 1];
        s1 += c[nt][0] * av0 + c[nt][1] * av1;
        d1 += c[nt][0] * dv0 + c[nt][1] * dv1;
        s2 += c[nt][2] * av0 + c[nt][3] * av1;
        d2 += c[nt][2] * dv0 + c[nt][3] * dv1;
    }
#pragma unroll
    for (int off = 1; off < 4; off <<= 1) {
        s1 += __shfl_xor_sync(~0u, s1, off); d1 += __shfl_xor_sync(~0u, d1, off);
        s2 += __shfl_xor_sync(~0u, s2, off); d2 += __shfl_xor_sync(~0u, d2, off);
    }
    if (t == 0) {
        int rl1 = wm * 16 + g, rl2 = rl1 + 8;
        sp[rl1][wn] = s1; dp[rl1][wn] = d1;
        sp[rl2][wn] = s2; dp[rl2][wn] = d2;
    }
    __syncthreads();
    if (tid < 64 && row0 + tid < M) {
        g_as2[row0 + tid] = sp[tid][0] + sp[tid][1];
        g_ad2[row0 + tid] = dp[tid][0] + dp[tid][1];
    }
}

// ---------------- layer1 gather v3: warp/node, 4 edges/warp, 8 rows in flight
// 8 lanes x 32B (2x LDG.128) cover one 256B fp16 row; quads process edges.
__global__ void k_gather1(const float* __restrict__ b1, int base, int count) {
    int w = base + blockIdx.x * 8 + (threadIdx.x >> 5);
    int lane = threadIdx.x & 31;
    if (w >= base + count) return;
    int q = lane >> 3;             // edge slot 0..3
    int sl = lane & 7;             // halfs sl*16 .. sl*16+15
    int h = sl >> 1;               // head (2 lanes per head)
    float my_ad = __ldg(&g_ad1[w * 4 + h]);
    float den = 0.f;
    float acc[16];
#pragma unroll
    for (int j = 0; j < 16; j++) acc[j] = 0.f;
    if (q == 0) {
        float e_self = __expf(lrelu(__ldg(&g_as1[w * 4 + h]) + my_ad));
        den = e_self;
        float hv[16];
        ldh16nc(&g_h1[(size_t)w * 128 + sl * 16], hv);
#pragma unroll
        for (int j = 0; j < 16; j++) acc[j] = hv[j] * e_self;
    }
    int beg = g_roff[w], end = g_roff[w + 1];
    int i = beg + q;
    for (; i + 4 < end; i += 8) {
        int s0 = __ldg(&g_csrc[i]), s1 = __ldg(&g_csrc[i + 4]);
        float e0 = __expf(lrelu(__ldg(&g_as1[s0 * 4 + h]) + my_ad));
        float e1 = __expf(lrelu(__ldg(&g_as1[s1 * 4 + h]) + my_ad));
        den += e0 + e1;
        float h0[16], h1[16];
        ldh16nc(&g_h1[(size_t)s0 * 128 + sl * 16], h0);
        ldh16nc(&g_h1[(size_t)s1 * 128 + sl * 16], h1);
#pragma unroll
        for (int j = 0; j < 16; j++) acc[j] += h0[j] * e0 + h1[j] * e1;
    }
    for (; i < end; i += 4) {
        int s0 = __ldg(&g_csrc[i]);
        float e0 = __expf(lrelu(__ldg(&g_as1[s0 * 4 + h]) + my_ad));
        den += e0;
        float h0[16];
        ldh16nc(&g_h1[(size_t)s0 * 128 + sl * 16], h0);
#pragma unroll
        for (int j = 0; j < 16; j++) acc[j] += h0[j] * e0;
    }
    // combine across the 4 quads (same sl, different edges)
#pragma unroll
    for (int j = 0; j < 16; j++) {
        acc[j] += __shfl_xor_sync(~0u, acc[j], 8);
        acc[j] += __shfl_xor_sync(~0u, acc[j], 16);
    }
    den += __shfl_xor_sync(~0u, den, 8);
    den += __shfl_xor_sync(~0u, den, 16);
    if (q == 0) {
        float inv = __frcp_rn(den + 1e-16f);
        float o[16];
#pragma unroll
        for (int j = 0; j < 16; j += 4) {
            float4 bb = *(const float4*)&b1[sl * 16 + j];
            o[j]     = acc[j]     * inv + bb.x;
            o[j + 1] = acc[j + 1] * inv + bb.y;
            o[j + 2] = acc[j + 2] * inv + bb.z;
            o[j + 3] = acc[j + 3] * inv + bb.w;
        }
        sth8(&g_o1[(size_t)w * 128 + sl * 16], o);
        sth8(&g_o1[(size_t)w * 128 + sl * 16 + 8], o + 8);
    }
}

// ---------------- layer2 gather + next-replay state reset --------------------
__global__ void k_gather2(const float* __restrict__ b2, float* __restrict__ out) {
    {
        int gidx = blockIdx.x * blockDim.x + threadIdx.x;
        if (gidx < NN) g_deg[gidx] = 0;
        if (gidx == 0) g_tick = 0;
    }
    int w = blockIdx.x * 8 + (threadIdx.x >> 5);
    int lane = threadIdx.x & 31;
    if (w >= NN) return;
    int q = lane >> 3;
    int sl = lane & 7;
    float my_ad = __ldg(&g_ad2[w]);
    float den = 0.f;
    float acc[8];
#pragma unroll
    for (int j = 0; j < 8; j++) acc[j] = 0.f;
    if (q == 0) {
        float e_self = __expf(lrelu(__ldg(&g_as2[w]) + my_ad));
        den = e_self;
        float hv[8];
        ldh8nc(&g_h2[(size_t)w * 64 + sl * 8], hv);
#pragma unroll
        for (int j = 0; j < 8; j++) acc[j] = hv[j] * e_self;
    }
    int beg = g_roff[w], end = g_roff[w + 1];
    int i = beg + q;
    for (; i + 4 < end; i += 8) {
        int s0 = __ldg(&g_csrc[i]), s1 = __ldg(&g_csrc[i + 4]);
        float e0 = __expf(lrelu(__ldg(&g_as2[s0]) + my_ad));
        float e1 = __expf(lrelu(__ldg(&g_as2[s1]) + my_ad));
        den += e0 + e1;
        float h0[8], h1[8];
        ldh8nc(&g_h2[(size_t)s0 * 64 + sl * 8], h0);
        ldh8nc(&g_h2[(size_t)s1 * 64 + sl * 8], h1);
#pragma unroll
        for (int j = 0; j < 8; j++) acc[j] += h0[j] * e0 + h1[j] * e1;
    }
    for (; i < end; i += 4) {
        int s0 = __ldg(&g_csrc[i]);
        float e0 = __expf(lrelu(__ldg(&g_as2[s0]) + my_ad));
        den += e0;
        float h0[8];
        ldh8nc(&g_h2[(size_t)s0 * 64 + sl * 8], h0);
#pragma unroll
        for (int j = 0; j < 8; j++) acc[j] += h0[j] * e0;
    }
#pragma unroll
    for (int j = 0; j < 8; j++) {
        acc[j] += __shfl_xor_sync(~0u, acc[j], 8);
        acc[j] += __shfl_xor_sync(~0u, acc[j], 16);
    }
    den += __shfl_xor_sync(~0u, den, 8);
    den += __shfl_xor_sync(~0u, den, 16);
    if (q == 0) {
        float inv = __frcp_rn(den + 1e-16f);
        float4 bb0 = *(const float4*)&b2[sl * 8];
        float4 bb1 = *(const float4*)&b2[sl * 8 + 4];
        float4 o0 = make_float4(acc[0] * inv + bb0.x, acc[1] * inv + bb0.y,
                                acc[2] * inv + bb0.z, acc[3] * inv + bb0.w);
        float4 o1 = make_float4(acc[4] * inv + bb1.x, acc[5] * inv + bb1.y,
                                acc[6] * inv + bb1.z, acc[7] * inv + bb1.w);
        *(float4*)&out[(size_t)w * 64 + sl * 8]     = o0;
        *(float4*)&out[(size_t)w * 64 + sl * 8 + 4] = o1;
    }
}

// ---------------- launch: CSR ∥ gemm1, then gather1/gemm2 pipelined ----------
extern "C" void kernel_launch(void* const* d_in, const int* in_sizes, int n_in,
                              void* d_out, int out_size) {
    const float* x    = (const float*)d_in[0];
    const void*  ei   = d_in[1];
    const float* W1   = (const float*)d_in[2];
    const float* as1  = (const float*)d_in[3];
    const float* ad1  = (const float*)d_in[4];
    const float* b1   = (const float*)d_in[5];
    const float* W2   = (const float*)d_in[6];
    const float* as2  = (const float*)d_in[7];
    const float* ad2  = (const float*)d_in[8];
    const float* b2   = (const float*)d_in[9];
    float* out = (float*)d_out;

    __half* p_h1;  cudaGetSymbolAddress((void**)&p_h1, g_h1);
    __half* p_o1;  cudaGetSymbolAddress((void**)&p_o1, g_o1);
    __half* p_h2;  cudaGetSymbolAddress((void**)&p_h2, g_h2);

    static cudaStream_t s2 = nullptr;
    static cudaEvent_t evF = nullptr, evG = nullptr, evJ = nullptr, evJ2 = nullptr;
    if (!s2) {
        cudaStreamCreate(&s2);
        cudaEventCreateWithFlags(&evF, cudaEventDisableTiming);
        cudaEventCreateWithFlags(&evG, cudaEventDisableTiming);
        cudaEventCreateWithFlags(&evJ, cudaEventDisableTiming);
        cudaEventCreateWithFlags(&evJ2, cudaEventDisableTiming);
    }

    cudaEventRecord(evF, 0);
    cudaStreamWaitEvent(s2, evF, 0);

    k_prep   <<<(EE + 255) / 256, 256, 0, s2>>>(ei);
    k_scanA  <<<NB2, 512, 0, s2>>>();
    k_scan3  <<<NB2, 512, 0, s2>>>();
    k_scatter<<<(EE / 2 + 255) / 256, 256, 0, s2>>>();
    cudaEventRecord(evJ, s2);

    k_gemm1<<<(NN + 63) / 64, 256>>>(x, W1, p_h1, as1, ad1, NN);
    cudaEventRecord(evG, 0);

    cudaStreamWaitEvent(0, evJ, 0);
    cudaStreamWaitEvent(s2, evG, 0);

    k_gather1<<<NH / 8, 256>>>(b1, 0, NH);
    k_gather1<<<(NN - NH + 7) / 8, 256, 0, s2>>>(b1, NH, NN - NH);
    k_gemm2<<<NH / 64, 256>>>(p_o1, W2, p_h2, as2, ad2, 0, NN);
    k_gemm2<<<(NN - NH + 63) / 64, 256, 0, s2>>>(p_o1, W2, p_h2, as2, ad2, NH, NN);
    cudaEventRecord(evJ2, s2);
    cudaStreamWaitEvent(0, evJ2, 0);

    k_gather2<<<(NN + 7) / 8, 256>>>(b2, out);
}

// round 14
// speedup vs baseline: 1.0249x; 1.0249x over previous
#include <cuda_runtime.h>
#include <cuda_fp16.h>
#include <math.h>

#define NN 100000
#define EE 1600000
#define HC 128
#define F2 64
#define NEG_SLOPE 0.2f
#define NB2 ((NN + 511) / 512)   // 196 scan blocks (512 thr)
#define NH 50048                 // gather1/gemm2 pipeline split (64-aligned)

// ---------------- scratch (device globals; no allocation allowed) ----------
__device__ __half g_h1[NN * HC];
__device__ __half g_o1[NN * HC];
__device__ __half g_h2[NN * F2];
__device__ float  g_as1[NN * 4], g_ad1[NN * 4];
__device__ float  g_as2[NN], g_ad2[NN];
__device__ int    g_esrc[EE];
__device__ unsigned g_drk[EE];         // dst | (rank << 17)
__device__ int    g_deg[NN];           // zero at entry (BSS / gather2 tail)
__device__ int    g_roff[NN + 1];
__device__ int    g_bsum[NB2];
__device__ int    g_boff[NB2];
__device__ int    g_tick;
__device__ int    g_csrc[EE];

// ---------------- helpers ---------------------------------------------------
__device__ __forceinline__ float lrelu(float x) {
    return x > 0.f ? x : NEG_SLOPE * x;
}
__device__ __forceinline__ int clampN(int v) {
    return v < 0 ? 0 : (v >= NN ? NN - 1 : v);
}
__device__ __forceinline__ float to_tf32(float x) {
    float r; asm("cvt.rna.tf32.f32 %0, %1;" : "=f"(r) : "f"(x)); return r;
}
__device__ __forceinline__ void mma_tf32(float* c, unsigned a0, unsigned a1,
                                         unsigned a2, unsigned a3,
                                         unsigned b0, unsigned b1) {
    asm volatile(
        "mma.sync.aligned.m16n8k8.row.col.f32.tf32.tf32.f32 "
        "{%0,%1,%2,%3}, {%4,%5,%6,%7}, {%8,%9}, {%0,%1,%2,%3};"
        : "+f"(c[0]), "+f"(c[1]), "+f"(c[2]), "+f"(c[3])
        : "r"(a0), "r"(a1), "r"(a2), "r"(a3), "r"(b0), "r"(b1));
}
__device__ __forceinline__ float4 ldh4(const __half* p) {
    uint2 u = *(const uint2*)p;
    float2 a = __half22float2(*(__half2*)&u.x);
    float2 b = __half22float2(*(__half2*)&u.y);
    return make_float4(a.x, a.y, b.x, b.y);
}
// nc load of 8 consecutive halfs (16B aligned) -> 8 floats
__device__ __forceinline__ void ldh8nc(const __half* p, float* f) {
    uint4 u = __ldg((const uint4*)p);
    float2 a = __half22float2(*(__half2*)&u.x);
    float2 b = __half22float2(*(__half2*)&u.y);
    float2 c = __half22float2(*(__half2*)&u.z);
    float2 d = __half22float2(*(__half2*)&u.w);
    f[0] = a.x; f[1] = a.y; f[2] = b.x; f[3] = b.y;
    f[4] = c.x; f[5] = c.y; f[6] = d.x; f[7] = d.y;
}
__device__ __forceinline__ void sth8(__half* p, const float* f) {
    uint4 u;
    *(__half2*)&u.x = __floats2half2_rn(f[0], f[1]);
    *(__half2*)&u.y = __floats2half2_rn(f[2], f[3]);
    *(__half2*)&u.z = __floats2half2_rn(f[4], f[5]);
    *(__half2*)&u.w = __floats2half2_rn(f[6], f[7]);
    *(uint4*)p = u;
}

// ---------------- edge convert + histogram + rank capture (2 edges/thread) ---
__global__ void k_prep(const void* __restrict__ ei) {
    int i = (blockIdx.x * blockDim.x + threadIdx.x) * 2;
    if (i >= EE) return;
    const int* e32 = (const int*)ei;
    int is64 = 1;
#pragma unroll
    for (int k = 0; k < 8; k++)
        if (e32[2 * k + 1] != 0) is64 = 0;
    int s0, d0, s1, d1;
    if (is64) {
        // 16B loads: two int64 each (EE even -> aligned)
        longlong2 sv = __ldg((const longlong2*)((const long long*)ei + i));
        longlong2 dv = __ldg((const longlong2*)((const long long*)ei + EE + i));
        s0 = (int)sv.x; s1 = (int)sv.y;
        d0 = (int)dv.x; d1 = (int)dv.y;
    } else {
        int2 sv = __ldg((const int2*)(e32 + i));
        int2 dv = __ldg((const int2*)(e32 + EE + i));
        s0 = sv.x; s1 = sv.y;
        d0 = dv.x; d1 = dv.y;
    }
    s0 = clampN(s0); d0 = clampN(d0);
    s1 = clampN(s1); d1 = clampN(d1);
    g_esrc[i]     = s0;
    g_esrc[i + 1] = s1;
    unsigned r0 = (unsigned)atomicAdd(&g_deg[d0], 1);
    g_drk[i] = (unsigned)d0 | (r0 << 17);
    unsigned r1 = (unsigned)atomicAdd(&g_deg[d1], 1);
    g_drk[i + 1] = (unsigned)d1 | (r1 << 17);
}

// ---------------- scanA: per-block reduce + last-block scans block sums ------
__global__ void k_scanA() {
    __shared__ int sh[512];
    __shared__ int last;
    int b = blockIdx.x, t = threadIdx.x;
    int i = b * 512 + t;
    sh[t] = (i < NN) ? g_deg[i] : 0;
    __syncthreads();
#pragma unroll
    for (int off = 256; off; off >>= 1) {
        if (t < off) sh[t] += sh[t + off];
        __syncthreads();
    }
    if (t == 0) {
        g_bsum[b] = sh[0];
        __threadfence();
        last = (atomicAdd(&g_tick, 1) == NB2 - 1);
    }
    __syncthreads();
    if (last) {
        int v = (t < NB2) ? g_bsum[t] : 0;
        sh[t] = v;
        __syncthreads();
#pragma unroll
        for (int off = 1; off < 512; off <<= 1) {
            int x = (t >= off) ? sh[t - off] : 0;
            __syncthreads();
            sh[t] += x;
            __syncthreads();
        }
        if (t < NB2) g_boff[t] = sh[t] - v;   // exclusive
    }
}

// ---------------- scan3: in-block scan + offset -> row offsets ---------------
__global__ void k_scan3() {
    __shared__ int sh[512];
    int b = blockIdx.x, t = threadIdx.x;
    int i = b * 512 + t;
    int v = (i < NN) ? g_deg[i] : 0;
    sh[t] = v;
    __syncthreads();
#pragma unroll
    for (int off = 1; off < 512; off <<= 1) {
        int x = (t >= off) ? sh[t - off] : 0;
        __syncthreads();
        sh[t] += x;
        __syncthreads();
    }
    int excl = g_boff[b] + sh[t] - v;
    if (i < NN) {
        g_roff[i] = excl;
        if (i == NN - 1) g_roff[NN] = excl + v;
    }
}

// ---------------- scatter: atomic-free, packed, 2 edges/thread ---------------
__global__ void k_scatter() {
    int base = (blockIdx.x * blockDim.x + threadIdx.x) * 2;
    if (base >= EE) return;
    unsigned v0 = g_drk[base];
    int s0 = g_esrc[base];
    int p0 = g_roff[v0 & 131071u] + (int)(v0 >> 17);
    if (base + 1 < EE) {
        unsigned v1 = g_drk[base + 1];
        int s1 = g_esrc[base + 1];
        int p1 = g_roff[v1 & 131071u] + (int)(v1 >> 17);
        g_csrc[p0] = s0;
        g_csrc[p1] = s1;
    } else {
        g_csrc[p0] = s0;
    }
}

// ---------------- GEMM1 (tf32 mma) + fused att1 epilogue, fp16 C -------------
__global__ void k_gemm1(const float* __restrict__ A, const float* __restrict__ W,
                        __half* __restrict__ C,
                        const float* __restrict__ att_src, const float* __restrict__ att_dst,
                        int M) {
    __shared__ float As[64][36];
    __shared__ float Bs[32][132];
    int tid = threadIdx.x;
    int wid = tid >> 5, lane = tid & 31;
    int wm = wid >> 1, wn = wid & 1;
    int g = lane >> 2, t = lane & 3;
    int row0 = blockIdx.x * 64;
    float c[8][4];
#pragma unroll
    for (int i = 0; i < 8; i++)
#pragma unroll
        for (int j = 0; j < 4; j++) c[i][j] = 0.f;

    for (int k0 = 0; k0 < 128; k0 += 32) {
#pragma unroll
        for (int s = 0; s < 2; s++) {
            int f = tid + s * 256;
            int r = f >> 3, c4 = (f & 7) * 4;
            float4 v = make_float4(0.f, 0.f, 0.f, 0.f);
            if (row0 + r < M) v = *(const float4*)&A[(size_t)(row0 + r) * 128 + k0 + c4];
            v.x = to_tf32(v.x); v.y = to_tf32(v.y);
            v.z = to_tf32(v.z); v.w = to_tf32(v.w);
            *(float4*)&As[r][c4] = v;
        }
#pragma unroll
        for (int s = 0; s < 4; s++) {
            int f = tid + s * 256;
            int r = f >> 5, c4 = (f & 31) * 4;
            float4 v = *(const float4*)&W[(size_t)(k0 + r) * 128 + c4];
            v.x = to_tf32(v.x); v.y = to_tf32(v.y);
            v.z = to_tf32(v.z); v.w = to_tf32(v.w);
            *(float4*)&Bs[r][c4] = v;
        }
        __syncthreads();
#pragma unroll
        for (int kk = 0; kk < 32; kk += 8) {
            int ar = wm * 16;
            unsigned a0 = __float_as_uint(As[ar + g][kk + t]);
            unsigned a1 = __float_as_uint(As[ar + g + 8][kk + t]);
            unsigned a2 = __float_as_uint(As[ar + g][kk + t + 4]);
            unsigned a3 = __float_as_uint(As[ar + g + 8][kk + t + 4]);
#pragma unroll
            for (int nt = 0; nt < 8; nt++) {
                int n0 = wn * 64 + nt * 8;
                unsigned b0 = __float_as_uint(Bs[kk + t][n0 + g]);
                unsigned b1 = __float_as_uint(Bs[kk + t + 4][n0 + g]);
                mma_tf32(c[nt], a0, a1, a2, a3, b0, b1);
            }
        }
        __syncthreads();
    }
    int r1 = row0 + wm * 16 + g;
    int r2 = r1 + 8;
#pragma unroll
    for (int nt = 0; nt < 8; nt++) {
        int col = wn * 64 + nt * 8 + t * 2;
        if (r1 < M) *(__half2*)&C[(size_t)r1 * 128 + col] = __floats2half2_rn(c[nt][0], c[nt][1]);
        if (r2 < M) *(__half2*)&C[(size_t)r2 * 128 + col] = __floats2half2_rn(c[nt][2], c[nt][3]);
    }
    float s1a = 0.f, s1b = 0.f, d1a = 0.f, d1b = 0.f;
    float s2a = 0.f, s2b = 0.f, d2a = 0.f, d2b = 0.f;
#pragma unroll
    for (int nt = 0; nt < 8; nt++) {
        int col = wn * 64 + nt * 8 + t * 2;
        float av0 = att_src[col], av1 = att_src[col + 1];
        float dv0 = att_dst[col], dv1 = att_dst[col + 1];
        float ps1 = c[nt][0] * av0 + c[nt][1] * av1;
        float pd1 = c[nt][0] * dv0 + c[nt][1] * dv1;
        float ps2 = c[nt][2] * av0 + c[nt][3] * av1;
        float pd2 = c[nt][2] * dv0 + c[nt][3] * dv1;
        if (nt < 4) { s1a += ps1; d1a += pd1; s2a += ps2; d2a += pd2; }
        else        { s1b += ps1; d1b += pd1; s2b += ps2; d2b += pd2; }
    }
#pragma unroll
    for (int off = 1; off < 4; off <<= 1) {
        s1a += __shfl_xor_sync(~0u, s1a, off); s1b += __shfl_xor_sync(~0u, s1b, off);
        d1a += __shfl_xor_sync(~0u, d1a, off); d1b += __shfl_xor_sync(~0u, d1b, off);
        s2a += __shfl_xor_sync(~0u, s2a, off); s2b += __shfl_xor_sync(~0u, s2b, off);
        d2a += __shfl_xor_sync(~0u, d2a, off); d2b += __shfl_xor_sync(~0u, d2b, off);
    }
    if (t == 0) {
        int ha = 2 * wn, hb = 2 * wn + 1;
        if (r1 < M) {
            g_as1[r1 * 4 + ha] = s1a; g_as1[r1 * 4 + hb] = s1b;
            g_ad1[r1 * 4 + ha] = d1a; g_ad1[r1 * 4 + hb] = d1b;
        }
        if (r2 < M) {
            g_as1[r2 * 4 + ha] = s2a; g_as1[r2 * 4 + hb] = s2b;
            g_ad1[r2 * 4 + ha] = d2a; g_ad1[r2 * 4 + hb] = d2b;
        }
    }
}

// ---------------- GEMM2 (tf32 mma, fp16 A/C) + fused att2, row-range ---------
__global__ void k_gemm2(const __half* __restrict__ A, const float* __restrict__ W,
                        __half* __restrict__ C,
                        const float* __restrict__ att_src, const float* __restrict__ att_dst,
                        int base, int M) {
    __shared__ float As[64][36];
    __shared__ float Bs[32][68];
    __shared__ float sp[64][2], dp[64][2];
    int tid = threadIdx.x;
    int wid = tid >> 5, lane = tid & 31;
    int wm = wid >> 1, wn = wid & 1;
    int g = lane >> 2, t = lane & 3;
    int row0 = base + blockIdx.x * 64;
    float c[4][4];
#pragma unroll
    for (int i = 0; i < 4; i++)
#pragma unroll
        for (int j = 0; j < 4; j++) c[i][j] = 0.f;

    for (int k0 = 0; k0 < 128; k0 += 32) {
#pragma unroll
        for (int s = 0; s < 2; s++) {
            int f = tid + s * 256;
            int r = f >> 3, c4 = (f & 7) * 4;
            float4 v = make_float4(0.f, 0.f, 0.f, 0.f);
            if (row0 + r < M) {
                float4 u = ldh4(&A[(size_t)(row0 + r) * 128 + k0 + c4]);
                v.x = u.x > 0.f ? u.x : expm1f(u.x);
                v.y = u.y > 0.f ? u.y : expm1f(u.y);
                v.z = u.z > 0.f ? u.z : expm1f(u.z);
                v.w = u.w > 0.f ? u.w : expm1f(u.w);
            }
            v.x = to_tf32(v.x); v.y = to_tf32(v.y);
            v.z = to_tf32(v.z); v.w = to_tf32(v.w);
            *(float4*)&As[r][c4] = v;
        }
#pragma unroll
        for (int s = 0; s < 2; s++) {
            int f = tid + s * 256;
            int r = f >> 4, c4 = (f & 15) * 4;
            float4 v = *(const float4*)&W[(size_t)(k0 + r) * 64 + c4];
            v.x = to_tf32(v.x); v.y = to_tf32(v.y);
            v.z = to_tf32(v.z); v.w = to_tf32(v.w);
            *(float4*)&Bs[r][c4] = v;
        }
        __syncthreads();
#pragma unroll
        for (int kk = 0; kk < 32; kk += 8) {
            int ar = wm * 16;
            unsigned a0 = __float_as_uint(As[ar + g][kk + t]);
            unsigned a1 = __float_as_uint(As[ar + g + 8][kk + t]);
            unsigned a2 = __float_as_uint(As[ar + g][kk + t + 4]);
            unsigned a3 = __float_as_uint(As[ar + g + 8][kk + t + 4]);
#pragma unroll
            for (int nt = 0; nt < 4; nt++) {
                int n0 = wn * 32 + nt * 8;
                unsigned b0 = __float_as_uint(Bs[kk + t][n0 + g]);
                unsigned b1 = __float_as_uint(Bs[kk + t + 4][n0 + g]);
                mma_tf32(c[nt], a0, a1, a2, a3, b0, b1);
            }
        }
        __syncthreads();
    }
    int r1 = row0 + wm * 16 + g;
    int r2 = r1 + 8;
    float s1 = 0.f, d1 = 0.f, s2 = 0.f, d2 = 0.f;
#pragma unroll
    for (int nt = 0; nt < 4; nt++) {
        int col = wn * 32 + nt * 8 + t * 2;
        if (r1 < M) *(__half2*)&C[(size_t)r1 * 64 + col] = __floats2half2_rn(c[nt][0], c[nt][1]);
        if (r2 < M) *(__half2*)&C[(size_t)r2 * 64 + col] = __floats2half2_rn(c[nt][2], c[nt][3]);
        float av0 = att_src[col], av1 = att_src[col + 1];
        float dv0 = att_dst[col], dv1 = att_dst[col + 1];
        s1 += c[nt][0] * av0 + c[nt][1] * av1;
        d1 += c[nt][0] * dv0 + c[nt][1] * dv1;
        s2 += c[nt][2] * av0 + c[nt][3] * av1;
        d2 += c[nt][2] * dv0 + c[nt][3] * dv1;
    }
#pragma unroll
    for (int off = 1; off < 4; off <<= 1) {
        s1 += __shfl_xor_sync(~0u, s1, off); d1 += __shfl_xor_sync(~0u, d1, off);
        s2 += __shfl_xor_sync(~0u, s2, off); d2 += __shfl_xor_sync(~0u, d2, off);
    }
    if (t == 0) {
        int rl1 = wm * 16 + g, rl2 = rl1 + 8;
        sp[rl1][wn] = s1; dp[rl1][wn] = d1;
        sp[rl2][wn] = s2; dp[rl2][wn] = d2;
    }
    __syncthreads();
    if (tid < 64 && row0 + tid < M) {
        g_as2[row0 + tid] = sp[tid][0] + sp[tid][1];
        g_ad2[row0 + tid] = dp[tid][0] + dp[tid][1];
    }
}

// ---------------- layer1 gather (R11 shape): warp/node, 2 edges, LDG.128 -----
__global__ void k_gather1(const float* __restrict__ b1, int base, int count) {
    int w = base + blockIdx.x * 8 + (threadIdx.x >> 5);
    int lane = threadIdx.x & 31;
    if (w >= base + count) return;
    int half = lane >> 4;
    int sl = lane & 15;
    int h = sl >> 2;
    float my_ad = __ldg(&g_ad1[w * 4 + h]);
    float den = 0.f;
    float acc[8];
#pragma unroll
    for (int j = 0; j < 8; j++) acc[j] = 0.f;
    if (half == 0) {
        float e_self = __expf(lrelu(__ldg(&g_as1[w * 4 + h]) + my_ad));
        den = e_self;
        float hv[8];
        ldh8nc(&g_h1[(size_t)w * 128 + sl * 8], hv);
#pragma unroll
        for (int j = 0; j < 8; j++) acc[j] = hv[j] * e_self;
    }
    int beg = g_roff[w], end = g_roff[w + 1];
    int i = beg + half;
    for (; i + 2 < end; i += 4) {
        int s0 = __ldg(&g_csrc[i]), s1 = __ldg(&g_csrc[i + 2]);
        float e0 = __expf(lrelu(__ldg(&g_as1[s0 * 4 + h]) + my_ad));
        float e1 = __expf(lrelu(__ldg(&g_as1[s1 * 4 + h]) + my_ad));
        den += e0 + e1;
        float h0[8], h1[8];
        ldh8nc(&g_h1[(size_t)s0 * 128 + sl * 8], h0);
        ldh8nc(&g_h1[(size_t)s1 * 128 + sl * 8], h1);
#pragma unroll
        for (int j = 0; j < 8; j++) acc[j] += h0[j] * e0 + h1[j] * e1;
    }
    for (; i < end; i += 2) {
        int s0 = __ldg(&g_csrc[i]);
        float e0 = __expf(lrelu(__ldg(&g_as1[s0 * 4 + h]) + my_ad));
        den += e0;
        float h0[8];
        ldh8nc(&g_h1[(size_t)s0 * 128 + sl * 8], h0);
#pragma unroll
        for (int j = 0; j < 8; j++) acc[j] += h0[j] * e0;
    }
#pragma unroll
    for (int j = 0; j < 8; j++) acc[j] += __shfl_xor_sync(~0u, acc[j], 16);
    den += __shfl_xor_sync(~0u, den, 16);
    if (half == 0) {
        float inv = __frcp_rn(den + 1e-16f);
        float4 bb0 = *(const float4*)&b1[sl * 8];
        float4 bb1 = *(const float4*)&b1[sl * 8 + 4];
        float o[8];
        o[0] = acc[0] * inv + bb0.x; o[1] = acc[1] * inv + bb0.y;
        o[2] = acc[2] * inv + bb0.z; o[3] = acc[3] * inv + bb0.w;
        o[4] = acc[4] * inv + bb1.x; o[5] = acc[5] * inv + bb1.y;
        o[6] = acc[6] * inv + bb1.z; o[7] = acc[7] * inv + bb1.w;
        sth8(&g_o1[(size_t)w * 128 + sl * 8], o);
    }
}

// ---------------- layer2 gather + next-replay state reset --------------------
__global__ void k_gather2(const float* __restrict__ b2, float* __restrict__ out) {
    {
        int gidx = blockIdx.x * blockDim.x + threadIdx.x;
        if (gidx < NN) g_deg[gidx] = 0;
        if (gidx == 0) g_tick = 0;
    }
    int w = blockIdx.x * 8 + (threadIdx.x >> 5);
    int lane = threadIdx.x & 31;
    if (w >= NN) return;
    int q = lane >> 3;
    int sl = lane & 7;
    float my_ad = __ldg(&g_ad2[w]);
    float den = 0.f;
    float acc[8];
#pragma unroll
    for (int j = 0; j < 8; j++) acc[j] = 0.f;
    if (q == 0) {
        float e_self = __expf(lrelu(__ldg(&g_as2[w]) + my_ad));
        den = e_self;
        float hv[8];
        ldh8nc(&g_h2[(size_t)w * 64 + sl * 8], hv);
#pragma unroll
        for (int j = 0; j < 8; j++) acc[j] = hv[j] * e_self;
    }
    int beg = g_roff[w], end = g_roff[w + 1];
    int i = beg + q;
    for (; i + 4 < end; i += 8) {
        int s0 = __ldg(&g_csrc[i]), s1 = __ldg(&g_csrc[i + 4]);
        float e0 = __expf(lrelu(__ldg(&g_as2[s0]) + my_ad));
        float e1 = __expf(lrelu(__ldg(&g_as2[s1]) + my_ad));
        den += e0 + e1;
        float h0[8], h1[8];
        ldh8nc(&g_h2[(size_t)s0 * 64 + sl * 8], h0);
        ldh8nc(&g_h2[(size_t)s1 * 64 + sl * 8], h1);
#pragma unroll
        for (int j = 0; j < 8; j++) acc[j] += h0[j] * e0 + h1[j] * e1;
    }
    for (; i < end; i += 4) {
        int s0 = __ldg(&g_csrc[i]);
        float e0 = __expf(lrelu(__ldg(&g_as2[s0]) + my_ad));
        den += e0;
        float h0[8];
        ldh8nc(&g_h2[(size_t)s0 * 64 + sl * 8], h0);
#pragma unroll
        for (int j = 0; j < 8; j++) acc[j] += h0[j] * e0;
    }
#pragma unroll
    for (int j = 0; j < 8; j++) {
        acc[j] += __shfl_xor_sync(~0u, acc[j], 8);
        acc[j] += __shfl_xor_sync(~0u, acc[j], 16);
    }
    den += __shfl_xor_sync(~0u, den, 8);
    den += __shfl_xor_sync(~0u, den, 16);
    if (q == 0) {
        float inv = __frcp_rn(den + 1e-16f);
        float4 bb0 = *(const float4*)&b2[sl * 8];
        float4 bb1 = *(const float4*)&b2[sl * 8 + 4];
        float4 o0 = make_float4(acc[0] * inv + bb0.x, acc[1] * inv + bb0.y,
                                acc[2] * inv + bb0.z, acc[3] * inv + bb0.w);
        float4 o1 = make_float4(acc[4] * inv + bb1.x, acc[5] * inv + bb1.y,
                                acc[6] * inv + bb1.z, acc[7] * inv + bb1.w);
        *(float4*)&out[(size_t)w * 64 + sl * 8]     = o0;
        *(float4*)&out[(size_t)w * 64 + sl * 8 + 4] = o1;
    }
}

// ---------------- launch: CSR ∥ gemm1, then gather1/gemm2 pipelined ----------
extern "C" void kernel_launch(void* const* d_in, const int* in_sizes, int n_in,
                              void* d_out, int out_size) {
    const float* x    = (const float*)d_in[0];
    const void*  ei   = d_in[1];
    const float* W1   = (const float*)d_in[2];
    const float* as1  = (const float*)d_in[3];
    const float* ad1  = (const float*)d_in[4];
    const float* b1   = (const float*)d_in[5];
    const float* W2   = (const float*)d_in[6];
    const float* as2  = (const float*)d_in[7];
    const float* ad2  = (const float*)d_in[8];
    const float* b2   = (const float*)d_in[9];
    float* out = (float*)d_out;

    __half* p_h1;  cudaGetSymbolAddress((void**)&p_h1, g_h1);
    __half* p_o1;  cudaGetSymbolAddress((void**)&p_o1, g_o1);
    __half* p_h2;  cudaGetSymbolAddress((void**)&p_h2, g_h2);

    static cudaStream_t s2 = nullptr;
    static cudaEvent_t evF = nullptr, evG = nullptr, evJ = nullptr, evJ2 = nullptr;
    if (!s2) {
        cudaStreamCreate(&s2);
        cudaEventCreateWithFlags(&evF, cudaEventDisableTiming);
        cudaEventCreateWithFlags(&evG, cudaEventDisableTiming);
        cudaEventCreateWithFlags(&evJ, cudaEventDisableTiming);
        cudaEventCreateWithFlags(&evJ2, cudaEventDisableTiming);
    }

    cudaEventRecord(evF, 0);
    cudaStreamWaitEvent(s2, evF, 0);

    k_prep   <<<(EE / 2 + 255) / 256, 256, 0, s2>>>(ei);
    k_scanA  <<<NB2, 512, 0, s2>>>();
    k_scan3  <<<NB2, 512, 0, s2>>>();
    k_scatter<<<(EE / 2 + 255) / 256, 256, 0, s2>>>();
    cudaEventRecord(evJ, s2);

    k_gemm1<<<(NN + 63) / 64, 256>>>(x, W1, p_h1, as1, ad1, NN);
    cudaEventRecord(evG, 0);

    cudaStreamWaitEvent(0, evJ, 0);
    cudaStreamWaitEvent(s2, evG, 0);

    k_gather1<<<NH / 8, 256>>>(b1, 0, NH);
    k_gather1<<<(NN - NH + 7) / 8, 256, 0, s2>>>(b1, NH, NN - NH);
    k_gemm2<<<NH / 64, 256>>>(p_o1, W2, p_h2, as2, ad2, 0, NN);
    k_gemm2<<<(NN - NH + 63) / 64, 256, 0, s2>>>(p_o1, W2, p_h2, as2, ad2, NH, NN);
    cudaEventRecord(evJ2, s2);
    cudaStreamWaitEvent(0, evJ2, 0);

    k_gather2<<<(NN + 7) / 8, 256>>>(b2, out);
}